// round 2
// baseline (speedup 1.0000x reference)
#include <cuda_runtime.h>
#include <cstdint>

// Two-pass DCN CrossLayer:
//   alpha(row) = f(d0,d1,d2; c01,c012), out = alpha*x + betasum
// K1: warp-per-row triple-dot -> g_alpha[row]
// K2: block-per-8-rows elementwise axpy, betasum held in registers.

#define F_DIM 1024
#define NVEC  256            // F/4 float4 per row
#define K1_THREADS 512
#define K1_WARPS   16
#define K2_THREADS 256
#define K2_ROWS    8
#define MAX_B 65536

__device__ float g_alpha[MAX_B];

// ---------------- Kernel 1: alphas ----------------
__global__ __launch_bounds__(K1_THREADS)
void alpha_kernel(const float* __restrict__ x,
                  const float* __restrict__ kernels,
                  const float* __restrict__ bias,
                  int B)
{
    __shared__ float4 sw0[NVEC];
    __shared__ float4 sw1[NVEC];
    __shared__ float4 sw2[NVEC];
    __shared__ float  sred[2 * K1_WARPS];
    __shared__ float  sc01, sc012;

    const int tid = threadIdx.x;
    const int wid = tid >> 5;
    const int lid = tid & 31;

    // stage weights, accumulate cross constants c01 = b0.w1, c012 = (b0+b1).w2
    float pc01 = 0.f, pc012 = 0.f;
    float* fw0 = reinterpret_cast<float*>(sw0);
    float* fw1 = reinterpret_cast<float*>(sw1);
    float* fw2 = reinterpret_cast<float*>(sw2);
    #pragma unroll
    for (int e = tid; e < F_DIM; e += K1_THREADS) {
        float w0 = __ldg(&kernels[e]);
        float w1 = __ldg(&kernels[F_DIM + e]);
        float w2 = __ldg(&kernels[2 * F_DIM + e]);
        float b0 = __ldg(&bias[e]);
        float b1 = __ldg(&bias[F_DIM + e]);
        fw0[e] = w0; fw1[e] = w1; fw2[e] = w2;
        pc01  = fmaf(b0, w1, pc01);
        pc012 = fmaf(b0 + b1, w2, pc012);
    }
    #pragma unroll
    for (int off = 16; off; off >>= 1) {
        pc01  += __shfl_xor_sync(0xFFFFFFFFu, pc01,  off);
        pc012 += __shfl_xor_sync(0xFFFFFFFFu, pc012, off);
    }
    if (lid == 0) { sred[wid] = pc01; sred[K1_WARPS + wid] = pc012; }
    __syncthreads();
    if (tid == 0) {
        float a = 0.f, b = 0.f;
        #pragma unroll
        for (int i = 0; i < K1_WARPS; i++) { a += sred[i]; b += sred[K1_WARPS + i]; }
        sc01 = a; sc012 = b;
    }
    __syncthreads();

    const int row = blockIdx.x * K1_WARPS + wid;
    if (row >= B) return;

    const float4* __restrict__ xr =
        reinterpret_cast<const float4*>(x + (size_t)row * F_DIM);

    float p0 = 0.f, p1 = 0.f, p2 = 0.f;
    #pragma unroll
    for (int k = 0; k < 8; k++) {
        const int idx = k * 32 + lid;
        float4 xv = xr[idx];
        float4 a = sw0[idx];
        float4 b = sw1[idx];
        float4 c = sw2[idx];
        p0 = fmaf(xv.x, a.x, fmaf(xv.y, a.y, fmaf(xv.z, a.z, fmaf(xv.w, a.w, p0))));
        p1 = fmaf(xv.x, b.x, fmaf(xv.y, b.y, fmaf(xv.z, b.z, fmaf(xv.w, b.w, p1))));
        p2 = fmaf(xv.x, c.x, fmaf(xv.y, c.y, fmaf(xv.z, c.z, fmaf(xv.w, c.w, p2))));
    }
    #pragma unroll
    for (int off = 16; off; off >>= 1) {
        p0 += __shfl_xor_sync(0xFFFFFFFFu, p0, off);
        p1 += __shfl_xor_sync(0xFFFFFFFFu, p1, off);
        p2 += __shfl_xor_sync(0xFFFFFFFFu, p2, off);
    }

    if (lid == 0) {
        const float t1    = 1.f + p0;
        const float s1    = fmaf(t1, p1, sc01);
        const float t2    = t1 + s1;
        const float s2    = fmaf(t2, p2, sc012);
        g_alpha[row]      = t2 + s2;
    }
}

// ---------------- Kernel 2: out = alpha*x + betasum ----------------
__global__ __launch_bounds__(K2_THREADS)
void axpy_kernel(const float* __restrict__ x,
                 const float* __restrict__ bias,
                 float* __restrict__ out,
                 int B)
{
    const int t = threadIdx.x;             // float4 column index 0..255

    // betasum float4 for this column, once, into registers (L2-hit loads)
    const float4* __restrict__ b4 = reinterpret_cast<const float4*>(bias);
    float4 bs0 = __ldg(&b4[t]);
    float4 bs1 = __ldg(&b4[NVEC + t]);
    float4 bs2 = __ldg(&b4[2 * NVEC + t]);
    float4 bs;
    bs.x = bs0.x + bs1.x + bs2.x;
    bs.y = bs0.y + bs1.y + bs2.y;
    bs.z = bs0.z + bs1.z + bs2.z;
    bs.w = bs0.w + bs1.w + bs2.w;

    const int row0 = blockIdx.x * K2_ROWS;
    const float4* __restrict__ x4 = reinterpret_cast<const float4*>(x);
    float4* __restrict__ o4       = reinterpret_cast<float4*>(out);

    // load alphas (uniform per iteration) and x tiles with full ILP
    float a[K2_ROWS];
    #pragma unroll
    for (int k = 0; k < K2_ROWS; k++) {
        int r = row0 + k;
        a[k] = (r < B) ? __ldg(&g_alpha[r]) : 0.f;
    }

    #pragma unroll
    for (int k = 0; k < K2_ROWS; k++) {
        const int r = row0 + k;
        if (r >= B) break;
        const size_t idx = (size_t)r * NVEC + t;
        float4 xv = x4[idx];
        float4 o;
        o.x = fmaf(a[k], xv.x, bs.x);
        o.y = fmaf(a[k], xv.y, bs.y);
        o.z = fmaf(a[k], xv.z, bs.z);
        o.w = fmaf(a[k], xv.w, bs.w);
        o4[idx] = o;
    }
}

extern "C" void kernel_launch(void* const* d_in, const int* in_sizes, int n_in,
                              void* d_out, int out_size)
{
    const float* x       = (const float*)d_in[0];
    const float* kernels = (const float*)d_in[1];
    const float* bias    = (const float*)d_in[2];
    float* out           = (float*)d_out;

    int B = in_sizes[0] / F_DIM;
    if (B > MAX_B) B = MAX_B;

    const int g1 = (B + K1_WARPS - 1) / K1_WARPS;
    alpha_kernel<<<g1, K1_THREADS>>>(x, kernels, bias, B);

    const int g2 = (B + K2_ROWS - 1) / K2_ROWS;
    axpy_kernel<<<g2, K2_THREADS>>>(x, bias, out, B);
}

// round 3
// speedup vs baseline: 1.2613x; 1.2613x over previous
#include <cuda_runtime.h>
#include <cstdint>

// Fused DCN CrossLayer, 2 warps per row:
//   alpha(row) = f(x.w0, x.w1, x.w2; c01, c012);  out = alpha*x + betasum
// Block = 512 thr = 16 warps = 8 rows. Warp owns half a row (512 cols),
// caches its 4 float4 of x in registers between dot phase and store phase.

#define F_DIM 1024
#define NVEC  256
#define THREADS 512
#define WARPS 16
#define ROWS_PER_BLOCK 8

__global__ __launch_bounds__(THREADS)
void cross_fused_kernel(const float* __restrict__ x,
                        const float* __restrict__ kernels,
                        const float* __restrict__ bias,
                        float* __restrict__ out,
                        int B)
{
    __shared__ float4 sw0[NVEC];
    __shared__ float4 sw1[NVEC];
    __shared__ float4 sw2[NVEC];
    __shared__ float4 sbs[NVEC];
    __shared__ float  sred[2 * WARPS];
    __shared__ float  sp[ROWS_PER_BLOCK][2][4];   // per-row, per-half partial dots
    __shared__ float  sc01, sc012;

    const int tid = threadIdx.x;
    const int wid = tid >> 5;
    const int lid = tid & 31;

    // ---- Stage w0,w1,w2,betasum into shared; accumulate cross constants ----
    {
        float pc01 = 0.f, pc012 = 0.f;
        float* fw0 = reinterpret_cast<float*>(sw0);
        float* fw1 = reinterpret_cast<float*>(sw1);
        float* fw2 = reinterpret_cast<float*>(sw2);
        float* fbs = reinterpret_cast<float*>(sbs);
        #pragma unroll
        for (int e = tid; e < F_DIM; e += THREADS) {
            float w0 = __ldg(&kernels[e]);
            float w1 = __ldg(&kernels[F_DIM + e]);
            float w2 = __ldg(&kernels[2 * F_DIM + e]);
            float b0 = __ldg(&bias[e]);
            float b1 = __ldg(&bias[F_DIM + e]);
            float b2 = __ldg(&bias[2 * F_DIM + e]);
            fw0[e] = w0; fw1[e] = w1; fw2[e] = w2;
            fbs[e] = b0 + b1 + b2;
            pc01  = fmaf(b0, w1, pc01);
            pc012 = fmaf(b0 + b1, w2, pc012);
        }
        #pragma unroll
        for (int off = 16; off; off >>= 1) {
            pc01  += __shfl_xor_sync(0xFFFFFFFFu, pc01,  off);
            pc012 += __shfl_xor_sync(0xFFFFFFFFu, pc012, off);
        }
        if (lid == 0) { sred[wid] = pc01; sred[WARPS + wid] = pc012; }
    }
    __syncthreads();
    if (tid == 0) {
        float a = 0.f, b = 0.f;
        #pragma unroll
        for (int i = 0; i < WARPS; i++) { a += sred[i]; b += sred[WARPS + i]; }
        sc01 = a; sc012 = b;
    }
    __syncthreads();

    // ---- Dot phase: warp = (row r, half h) ----
    const int r   = wid >> 1;
    const int h   = wid & 1;
    const int row = blockIdx.x * ROWS_PER_BLOCK + r;
    const bool active = (row < B);

    const float4* __restrict__ xr =
        reinterpret_cast<const float4*>(x) + (size_t)row * NVEC;

    float4 xs[4];
    if (active) {
        float p0 = 0.f, p1 = 0.f, p2 = 0.f;
        #pragma unroll
        for (int k = 0; k < 4; k++) {
            const int idx = h * 128 + k * 32 + lid;
            float4 xv = __ldcs(&xr[idx]);        // streaming: read-once
            xs[k] = xv;
            float4 a = sw0[idx];
            float4 b = sw1[idx];
            float4 c = sw2[idx];
            p0 = fmaf(xv.x, a.x, fmaf(xv.y, a.y, fmaf(xv.z, a.z, fmaf(xv.w, a.w, p0))));
            p1 = fmaf(xv.x, b.x, fmaf(xv.y, b.y, fmaf(xv.z, b.z, fmaf(xv.w, b.w, p1))));
            p2 = fmaf(xv.x, c.x, fmaf(xv.y, c.y, fmaf(xv.z, c.z, fmaf(xv.w, c.w, p2))));
        }
        #pragma unroll
        for (int off = 16; off; off >>= 1) {
            p0 += __shfl_xor_sync(0xFFFFFFFFu, p0, off);
            p1 += __shfl_xor_sync(0xFFFFFFFFu, p1, off);
            p2 += __shfl_xor_sync(0xFFFFFFFFu, p2, off);
        }
        if (lid == 0) {
            sp[r][h][0] = p0; sp[r][h][1] = p1; sp[r][h][2] = p2;
        }
    }
    __syncthreads();

    // ---- Combine halves -> alpha; store phase ----
    if (active) {
        const float d0 = sp[r][0][0] + sp[r][1][0];
        const float d1 = sp[r][0][1] + sp[r][1][1];
        const float d2 = sp[r][0][2] + sp[r][1][2];

        const float t1    = 1.f + d0;
        const float s1    = fmaf(t1, d1, sc01);
        const float t2    = t1 + s1;
        const float s2    = fmaf(t2, d2, sc012);
        const float alpha = t2 + s2;

        float4* __restrict__ orow =
            reinterpret_cast<float4*>(out) + (size_t)row * NVEC;
        #pragma unroll
        for (int k = 0; k < 4; k++) {
            const int idx = h * 128 + k * 32 + lid;
            float4 bv = sbs[idx];
            float4 o;
            o.x = fmaf(alpha, xs[k].x, bv.x);
            o.y = fmaf(alpha, xs[k].y, bv.y);
            o.z = fmaf(alpha, xs[k].z, bv.z);
            o.w = fmaf(alpha, xs[k].w, bv.w);
            __stcs(&orow[idx], o);               // streaming: write-once
        }
    }
}

extern "C" void kernel_launch(void* const* d_in, const int* in_sizes, int n_in,
                              void* d_out, int out_size)
{
    const float* x       = (const float*)d_in[0];
    const float* kernels = (const float*)d_in[1];
    const float* bias    = (const float*)d_in[2];
    float* out           = (float*)d_out;

    const int B = in_sizes[0] / F_DIM;
    const int grid = (B + ROWS_PER_BLOCK - 1) / ROWS_PER_BLOCK;
    cross_fused_kernel<<<grid, THREADS>>>(x, kernels, bias, out, B);
}

// round 4
// speedup vs baseline: 1.2626x; 1.0010x over previous
#include <cuda_runtime.h>
#include <cstdint>

// Column-major fused DCN CrossLayer.
// Thread t owns float4 column t (256 threads = full F=1024 row).
// Weights w0,w1,w2 and betasum for that column live in REGISTERS.
// Block processes CHUNK=32 rows in chunks of R=4:
//   dot phase:  4x LDG.128 (batched), 12 partial dots, warp-XOR reduce (12-way ILP)
//   combine:    warp 0 sums 8 warps' partials, computes 4 alphas
//   store:      out = alpha*x + betasum  (x still in registers)

#define F_DIM 1024
#define NVEC  256
#define THREADS 256
#define NWARPS 8
#define R 4
#define CHUNK 32

__device__ __forceinline__ float dot4(float4 a, float4 b, float acc) {
    return fmaf(a.x, b.x, fmaf(a.y, b.y, fmaf(a.z, b.z, fmaf(a.w, b.w, acc))));
}

__global__ __launch_bounds__(THREADS)
void cross_colmajor_kernel(const float* __restrict__ x,
                           const float* __restrict__ kernels,
                           const float* __restrict__ bias,
                           float* __restrict__ out,
                           int B)
{
    __shared__ float red[12][NWARPS];
    __shared__ float salpha[R];
    __shared__ float sc01, sc012;

    const int t   = threadIdx.x;        // float4 column 0..255
    const int wid = t >> 5;
    const int lid = t & 31;

    // ---- One-time: per-column weights into registers ----
    const float4* __restrict__ k4 = reinterpret_cast<const float4*>(kernels);
    const float4* __restrict__ b4 = reinterpret_cast<const float4*>(bias);
    const float4 w0 = __ldg(&k4[t]);
    const float4 w1 = __ldg(&k4[NVEC + t]);
    const float4 w2 = __ldg(&k4[2 * NVEC + t]);
    float4 b0 = __ldg(&b4[t]);
    float4 b1 = __ldg(&b4[NVEC + t]);
    float4 b2 = __ldg(&b4[2 * NVEC + t]);
    float4 bs;
    bs.x = b0.x + b1.x + b2.x;
    bs.y = b0.y + b1.y + b2.y;
    bs.z = b0.z + b1.z + b2.z;
    bs.w = b0.w + b1.w + b2.w;

    // cross constants: c01 = b0.w1, c012 = (b0+b1).w2
    {
        float pc01  = dot4(b0, w1, 0.f);
        float4 b01;
        b01.x = b0.x + b1.x; b01.y = b0.y + b1.y;
        b01.z = b0.z + b1.z; b01.w = b0.w + b1.w;
        float pc012 = dot4(b01, w2, 0.f);
        #pragma unroll
        for (int off = 16; off; off >>= 1) {
            pc01  += __shfl_xor_sync(0xFFFFFFFFu, pc01,  off);
            pc012 += __shfl_xor_sync(0xFFFFFFFFu, pc012, off);
        }
        if (lid == 0) { red[0][wid] = pc01; red[1][wid] = pc012; }
        __syncthreads();
        if (t == 0) {
            float a = 0.f, b = 0.f;
            #pragma unroll
            for (int i = 0; i < NWARPS; i++) { a += red[0][i]; b += red[1][i]; }
            sc01 = a; sc012 = b;
        }
        __syncthreads();
    }
    const float c01  = sc01;
    const float c012 = sc012;

    const float4* __restrict__ x4 = reinterpret_cast<const float4*>(x);
    float4* __restrict__ o4       = reinterpret_cast<float4*>(out);

    const int row0 = blockIdx.x * CHUNK;

    #pragma unroll 1
    for (int it = 0; it < CHUNK / R; ++it) {
        const int rbase = row0 + it * R;
        if (rbase >= B) break;

        // ---- Dot phase: 4 rows, batched loads ----
        float4 xs[R];
        float  p[3 * R];
        #pragma unroll
        for (int r = 0; r < R; r++) {
            const int rr = (rbase + r < B) ? (rbase + r) : (B - 1);
            xs[r] = __ldcs(&x4[(size_t)rr * NVEC + t]);
        }
        #pragma unroll
        for (int r = 0; r < R; r++) {
            p[r]         = dot4(xs[r], w0, 0.f);
            p[R + r]     = dot4(xs[r], w1, 0.f);
            p[2 * R + r] = dot4(xs[r], w2, 0.f);
        }
        // warp reduce all 12 partials (independent chains -> ILP hides SHFL lat)
        #pragma unroll
        for (int off = 16; off; off >>= 1) {
            #pragma unroll
            for (int j = 0; j < 3 * R; j++)
                p[j] += __shfl_xor_sync(0xFFFFFFFFu, p[j], off);
        }
        if (lid == 0) {
            #pragma unroll
            for (int j = 0; j < 3 * R; j++) red[j][wid] = p[j];
        }
        __syncthreads();

        // ---- Combine: warp 0 sums across warps, computes alphas ----
        if (wid == 0) {
            float val = 0.f;
            if (lid < 12) {
                #pragma unroll
                for (int w = 0; w < NWARPS; w++) val += red[lid][w];
            }
            const int r = lid & 3;
            const float d0 = __shfl_sync(0xFFFFFFFFu, val, r);
            const float d1 = __shfl_sync(0xFFFFFFFFu, val, R + r);
            const float d2 = __shfl_sync(0xFFFFFFFFu, val, 2 * R + r);
            if (lid < R) {
                const float t1 = 1.f + d0;
                const float s1 = fmaf(t1, d1, c01);
                const float t2 = t1 + s1;
                const float s2 = fmaf(t2, d2, c012);
                salpha[lid] = t2 + s2;
            }
        }
        __syncthreads();

        // ---- Store phase: x still in registers ----
        #pragma unroll
        for (int r = 0; r < R; r++) {
            const int rr = rbase + r;
            if (rr >= B) break;
            const float a = salpha[r];
            float4 o;
            o.x = fmaf(a, xs[r].x, bs.x);
            o.y = fmaf(a, xs[r].y, bs.y);
            o.z = fmaf(a, xs[r].z, bs.z);
            o.w = fmaf(a, xs[r].w, bs.w);
            __stcs(&o4[(size_t)rr * NVEC + t], o);
        }
    }
}

extern "C" void kernel_launch(void* const* d_in, const int* in_sizes, int n_in,
                              void* d_out, int out_size)
{
    const float* x       = (const float*)d_in[0];
    const float* kernels = (const float*)d_in[1];
    const float* bias    = (const float*)d_in[2];
    float* out           = (float*)d_out;

    const int B = in_sizes[0] / F_DIM;
    const int grid = (B + CHUNK - 1) / CHUNK;
    cross_colmajor_kernel<<<grid, THREADS>>>(x, kernels, bias, out, B);
}